// round 6
// baseline (speedup 1.0000x reference)
#include <cuda_runtime.h>
#include <math.h>

// ---------------- problem constants ----------------
#define B_TOTAL   16384
#define NSLOT     32
#define SDIM      64
#define HID       128
#define NKNOWN    9
#define NITER     3

#define PV_OFF    0
#define SLOTS_OFF (B_TOTAL*NKNOWN)                       // 147456
#define FREE_OFF  (B_TOTAL*NKNOWN + B_TOTAL*NSLOT*SDIM)  // 33701888

// scratch: gi[b][192] (upd == v for every slot since attn collapses to exactly 1.0)
__device__ float g_gi[(size_t)B_TOTAL * 192];

typedef unsigned long long u64;
union F2 { float f[2]; u64 u; };

__device__ __forceinline__ u64 pk2(float x) {
    u64 r; asm("mov.b64 %0, {%1, %1};" : "=l"(r) : "f"(x)); return r;
}
__device__ __forceinline__ void fma2(u64 &a, u64 b, u64 c) {
    asm("fma.rn.f32x2 %0, %1, %2, %0;" : "+l"(a) : "l"(b), "l"(c));
}
__device__ __forceinline__ float sigm_f(float x) { return 1.0f / (1.0f + __expf(-x)); }
__device__ __forceinline__ float tanh_f(float x) {
    float ax = fabsf(x);
    float t = __expf(-2.0f * ax);
    float r = __fdividef(1.0f - t, 1.0f + t);
    return copysignf(r, x);
}
__device__ __forceinline__ float gelu_f(float x) { return 0.5f * x * (1.0f + erff(x * 0.70710678118654752440f)); }

// ================= Kernel A2: per-batch x -> LN -> v -> gi (weights staged in smem) =================
#define SMEMA_FLOATS 36304

__global__ void __launch_bounds__(512, 1) kA2(
    const float* __restrict__ ws, const float* __restrict__ Wi, const float* __restrict__ bi,
    const float* __restrict__ g_in, const float* __restrict__ b_in,
    const float* __restrict__ Wv, const float* __restrict__ bv,
    const float* __restrict__ Wih, const float* __restrict__ bih)
{
    extern __shared__ float sa[];
    float* s_wi  = sa;
    float* s_wv  = sa + 16384;
    float* s_wih = sa + 20480;
    float* s_bi  = sa + 32768;
    float* s_bv  = sa + 32832;
    float* s_gin = sa + 32896;
    float* s_bin = sa + 32960;
    float* s_bih = sa + 33024;
    float* s_in  = sa + 33216;
    float* s_x   = sa + 35264;
    float* s_v   = sa + 35776;
    float* s_red = sa + 36288;

    int tid = threadIdx.x;
    int g = tid >> 6;
    int lane = tid & 63;
    size_t b = (size_t)blockIdx.x * 8 + g;

    for (int i = tid; i < 16384 / 4; i += 512) ((float4*)s_wi)[i]  = ((const float4*)Wi)[i];
    for (int i = tid; i < 4096 / 4;  i += 512) ((float4*)s_wv)[i]  = ((const float4*)Wv)[i];
    for (int i = tid; i < 12288 / 4; i += 512) ((float4*)s_wih)[i] = ((const float4*)Wih)[i];
    if (tid < 64)  s_bi[tid]  = bi[tid];
    if (tid >= 64  && tid < 128) s_bv[tid - 64]   = bv[tid - 64];
    if (tid >= 128 && tid < 192) s_gin[tid - 128] = g_in[tid - 128];
    if (tid >= 192 && tid < 256) s_bin[tid - 192] = b_in[tid - 192];
    if (tid >= 256 && tid < 448) s_bih[tid - 256] = bih[tid - 256];

    {
        const float4* src = (const float4*)(ws + (size_t)blockIdx.x * 8 * 256);
        for (int i = tid; i < 2048 / 4; i += 512) ((float4*)s_in)[i] = src[i];
    }
    __syncthreads();

    const float* in_g = s_in + g * 256;

    float acc = s_bi[lane];
    #pragma unroll 4
    for (int i = 0; i < 256; i++) acc += in_g[i] * s_wi[i * 64 + lane];

    float v = acc;
    #pragma unroll
    for (int o = 16; o; o >>= 1) v += __shfl_down_sync(0xffffffffu, v, o);
    if ((lane & 31) == 0) s_red[g * 2 + (lane >> 5)] = v;
    __syncthreads();
    float mu = (s_red[g * 2] + s_red[g * 2 + 1]) * (1.0f / 64.0f);
    __syncthreads();
    float dv = acc - mu;
    float vv = dv * dv;
    #pragma unroll
    for (int o = 16; o; o >>= 1) vv += __shfl_down_sync(0xffffffffu, vv, o);
    if ((lane & 31) == 0) s_red[g * 2 + (lane >> 5)] = vv;
    __syncthreads();
    float var = (s_red[g * 2] + s_red[g * 2 + 1]) * (1.0f / 64.0f);
    float inv = rsqrtf(var + 1e-5f);
    s_x[g * 64 + lane] = dv * inv * s_gin[lane] + s_bin[lane];
    __syncthreads();

    const float* x_g = s_x + g * 64;
    float vacc = s_bv[lane];
    #pragma unroll 4
    for (int d = 0; d < 64; d++) vacc += x_g[d] * s_wv[d * 64 + lane];
    s_v[g * 64 + lane] = vacc;
    __syncthreads();

    const float* v_g = s_v + g * 64;
    #pragma unroll
    for (int j = lane; j < 192; j += 64) {
        float a = s_bih[j];
        #pragma unroll 4
        for (int d = 0; d < 64; d++) a += v_g[d] * s_wih[d * 192 + j];
        g_gi[b * 192 + j] = a;
    }
}

// ================= Kernel Z: zero free_act accumulators =================
__global__ void kZ(float* __restrict__ out)
{
    int i = threadIdx.x;
    if (i < NSLOT - NKNOWN) out[FREE_OFF + i] = 0.0f;
}

// ================= Kernel B: fused GRU + MLP iterations + head (f32x2 packed) =================
// block = 256 threads = 8 batch elems x 32 slots (1 thread per slot)
#define SMEMB_FLOATS 47360

__global__ void __launch_bounds__(256, 1) kB(
    const float* __restrict__ eps, const float* __restrict__ mu0, const float* __restrict__ sg0,
    const float* __restrict__ Whh, const float* __restrict__ bhh,
    const float* __restrict__ W1, const float* __restrict__ b1,
    const float* __restrict__ W2, const float* __restrict__ b2,
    const float* __restrict__ gm, const float* __restrict__ bm,
    const float* __restrict__ Wh1, const float* __restrict__ bh1,
    const float* __restrict__ Wh2, const float* __restrict__ bh2,
    float* __restrict__ out)
{
    extern __shared__ float sm[];
    float* s_whh  = sm;
    float* s_w1   = sm + 12288;
    float* s_w2   = sm + 20480;
    float* s_bhh  = sm + 28672;
    float* s_b1   = sm + 28864;
    float* s_b2   = sm + 28992;
    float* s_gm   = sm + 29056;
    float* s_bm   = sm + 29120;
    float* s_gi   = sm + 29184;
    float* s_prev = sm + 30720;

    int tid = threadIdx.x;

    for (int i = tid; i < 12288 / 4; i += 256) ((float4*)s_whh)[i] = ((const float4*)Whh)[i];
    for (int i = tid; i < 8192 / 4;  i += 256) ((float4*)s_w1)[i]  = ((const float4*)W1)[i];
    for (int i = tid; i < 8192 / 4;  i += 256) ((float4*)s_w2)[i]  = ((const float4*)W2)[i];
    if (tid < 192) s_bhh[tid] = bhh[tid];
    if (tid < 128) s_b1[tid]  = b1[tid];
    if (tid < 64) { s_b2[tid] = b2[tid]; s_gm[tid] = gm[tid]; s_bm[tid] = bm[tid]; }
    {
        const float* gsrc = g_gi + (size_t)blockIdx.x * 8 * 192;
        for (int i = tid; i < 1536; i += 256) s_gi[i] = gsrc[i];
    }

    int bb = tid >> 5, s = tid & 31;
    size_t b = (size_t)blockIdx.x * 8 + bb;
    int pbase = tid * 65;

    {
        const float4* ep = (const float4*)(eps + (b * NSLOT + s) * SDIM);
        const float4* m4 = (const float4*)(mu0 + (size_t)s * SDIM);
        const float4* g4 = (const float4*)(sg0 + (size_t)s * SDIM);
        #pragma unroll
        for (int q = 0; q < 16; q++) {
            float4 e = ep[q], m = m4[q], sg = g4[q];
            s_prev[pbase + 4 * q + 0] = m.x + sg.x * e.x;
            s_prev[pbase + 4 * q + 1] = m.y + sg.y * e.y;
            s_prev[pbase + 4 * q + 2] = m.z + sg.z * e.z;
            s_prev[pbase + 4 * q + 3] = m.w + sg.w * e.w;
        }
    }
    __syncthreads();

    const float* gi = s_gi + bb * 192;
    F2 st[32];   // packed 64-float working buffer: st[m] holds dims {2m, 2m+1}

    for (int it = 0; it < NITER; ++it) {
        // ---- pass 1: r = sigmoid(gi_r + prev@Whh[:,0:64] + bhh_r) ----
        #pragma unroll
        for (int q = 0; q < 32; q++) {
            st[q].f[0] = s_bhh[2 * q]     + gi[2 * q];
            st[q].f[1] = s_bhh[2 * q + 1] + gi[2 * q + 1];
        }
        #pragma unroll 2
        for (int d = 0; d < 64; d++) {
            u64 p2 = pk2(s_prev[pbase + d]);
            const ulonglong2* w = (const ulonglong2*)(s_whh + d * 192);
            #pragma unroll
            for (int q = 0; q < 16; q++) {
                ulonglong2 ww = w[q];
                fma2(st[2 * q].u, ww.x, p2);
                fma2(st[2 * q + 1].u, ww.y, p2);
            }
        }
        #pragma unroll
        for (int q = 0; q < 32; q++) {
            st[q].f[0] = sigm_f(st[q].f[0]);
            st[q].f[1] = sigm_f(st[q].f[1]);
        }

        // ---- pass 2: z, n, new state (2 chunks of 32 outputs) ----
        #pragma unroll
        for (int jb = 0; jb < 2; jb++) {
            F2 az[16], an[16];
            #pragma unroll
            for (int qq = 0; qq < 16; qq++) {
                int j = jb * 32 + 2 * qq;
                az[qq].f[0] = s_bhh[64 + j]     + gi[64 + j];
                az[qq].f[1] = s_bhh[64 + j + 1] + gi[64 + j + 1];
                an[qq].f[0] = s_bhh[128 + j];        // gi_n added after r*(...)
                an[qq].f[1] = s_bhh[128 + j + 1];
            }
            #pragma unroll 2
            for (int d = 0; d < 64; d++) {
                u64 p2 = pk2(s_prev[pbase + d]);
                const ulonglong2* wz = (const ulonglong2*)(s_whh + d * 192 + 64  + jb * 32);
                const ulonglong2* wn = (const ulonglong2*)(s_whh + d * 192 + 128 + jb * 32);
                #pragma unroll
                for (int q = 0; q < 8; q++) {
                    ulonglong2 a = wz[q];
                    fma2(az[2 * q].u, a.x, p2);
                    fma2(az[2 * q + 1].u, a.y, p2);
                    ulonglong2 c = wn[q];
                    fma2(an[2 * q].u, c.x, p2);
                    fma2(an[2 * q + 1].u, c.y, p2);
                }
            }
            #pragma unroll
            for (int qq = 0; qq < 32; qq++) {
                int j = jb * 32 + qq;
                float z = sigm_f((qq & 1) ? az[qq >> 1].f[1] : az[qq >> 1].f[0]);
                float aa = (qq & 1) ? an[qq >> 1].f[1] : an[qq >> 1].f[0];
                float r = st[j >> 1].f[j & 1];
                float n = tanh_f(gi[128 + j] + r * aa);
                float pr = s_prev[pbase + j];
                st[j >> 1].f[j & 1] = (1.0f - z) * n + z * pr;
            }
        }

        // ---- LayerNorm + MLP residual ----
        float mu = 0.0f;
        #pragma unroll
        for (int q = 0; q < 32; q++) mu += st[q].f[0] + st[q].f[1];
        mu *= (1.0f / 64.0f);
        float var = 0.0f;
        #pragma unroll
        for (int q = 0; q < 32; q++) {
            float d0 = st[q].f[0] - mu, d1 = st[q].f[1] - mu;
            var += d0 * d0 + d1 * d1;
        }
        var *= (1.0f / 64.0f);
        float inv = rsqrtf(var + 1e-5f);
        #pragma unroll
        for (int q = 0; q < 32; q++) {
            s_prev[pbase + 2 * q]     = (st[q].f[0] - mu) * inv * s_gm[2 * q]     + s_bm[2 * q];
            s_prev[pbase + 2 * q + 1] = (st[q].f[1] - mu) * inv * s_gm[2 * q + 1] + s_bm[2 * q + 1];
        }
        #pragma unroll
        for (int q = 0; q < 32; q++) {
            st[q].f[0] += s_b2[2 * q];
            st[q].f[1] += s_b2[2 * q + 1];
        }

        // MLP: 4 chunks of 32 hidden units
        #pragma unroll
        for (int mb = 0; mb < 4; mb++) {
            F2 ah[16];
            #pragma unroll
            for (int qq = 0; qq < 16; qq++) {
                ah[qq].f[0] = s_b1[mb * 32 + 2 * qq];
                ah[qq].f[1] = s_b1[mb * 32 + 2 * qq + 1];
            }
            #pragma unroll 2
            for (int d = 0; d < 64; d++) {
                u64 p2 = pk2(s_prev[pbase + d]);
                const ulonglong2* w = (const ulonglong2*)(s_w1 + d * 128 + mb * 32);
                #pragma unroll
                for (int q = 0; q < 8; q++) {
                    ulonglong2 a = w[q];
                    fma2(ah[2 * q].u, a.x, p2);
                    fma2(ah[2 * q + 1].u, a.y, p2);
                }
            }
            #pragma unroll
            for (int hh = 0; hh < 32; hh++) {
                int h = mb * 32 + hh;
                float g = gelu_f((hh & 1) ? ah[hh >> 1].f[1] : ah[hh >> 1].f[0]);
                u64 g2 = pk2(g);
                const ulonglong2* w2 = (const ulonglong2*)(s_w2 + h * 64);
                // FIXED (R2/R3/R5 bug): w2 row = 64 floats = 16 ulonglong2, accumulate into ALL st[0..31]
                #pragma unroll
                for (int q = 0; q < 16; q++) {
                    ulonglong2 ww = w2[q];
                    fma2(st[2 * q].u, ww.x, g2);
                    fma2(st[2 * q + 1].u, ww.y, g2);
                }
            }
        }
        #pragma unroll
        for (int q = 0; q < 32; q++) {
            s_prev[pbase + 2 * q]     = st[q].f[0];
            s_prev[pbase + 2 * q + 1] = st[q].f[1];
        }
    }

    // ---- write final slots: all 64 floats ----
    {
        float4* o = (float4*)(out + SLOTS_OFF + (b * NSLOT + s) * SDIM);
        #pragma unroll
        for (int q = 0; q < 16; q++) {
            o[q] = make_float4(st[2 * q].f[0], st[2 * q].f[1],
                               st[2 * q + 1].f[0], st[2 * q + 1].f[1]);
        }
    }

    // ---- free_act partial (per thread, from registers before smem reuse) ----
    float freeval = 0.0f;
    if (s >= NKNOWN) {
        float sq = 0.0f;
        #pragma unroll
        for (int q = 0; q < 32; q++) sq += st[q].f[0] * st[q].f[0] + st[q].f[1] * st[q].f[1];
        freeval = sqrtf(sq) * (1.0f / (float)B_TOTAL);
    }

    // ---- head (reuse weight smem for Wh1 etc.) + block-level free_act reduction ----
    __syncthreads();
    float* s_hw1  = sm;           // 18432 floats (overlaps s_whh+s_w1, dead now)
    float* s_hb1  = sm + 18432;   // 288
    float* s_hw2  = sm + 18720;   // 288
    float* s_hb2  = sm + 19008;   // 9
    float* s_free = sm + 19072;   // 23
    for (int i = tid; i < 18432 / 4; i += 256) ((float4*)s_hw1)[i] = ((const float4*)Wh1)[i];
    for (int i = tid; i < 288; i += 256) { s_hb1[i] = bh1[i]; s_hw2[i] = Wh2[i]; }
    if (tid < 9) s_hb2[tid] = bh2[tid];
    if (tid >= 32 && tid < 55) s_free[tid - 32] = 0.0f;
    __syncthreads();

    if (s < NKNOWN) {
        int k = s;
        F2 ha[16];
        #pragma unroll
        for (int q = 0; q < 16; q++) {
            ha[q].f[0] = s_hb1[k * 32 + 2 * q];
            ha[q].f[1] = s_hb1[k * 32 + 2 * q + 1];
        }
        #pragma unroll 2
        for (int d = 0; d < 64; d++) {
            u64 p2 = pk2(s_prev[pbase + d]);
            const ulonglong2* w = (const ulonglong2*)(s_hw1 + k * 2048 + d * 32);
            #pragma unroll
            for (int q = 0; q < 8; q++) {
                ulonglong2 a = w[q];
                fma2(ha[2 * q].u, a.x, p2);
                fma2(ha[2 * q + 1].u, a.y, p2);
            }
        }
        float a2 = s_hb2[k];
        #pragma unroll
        for (int q = 0; q < 16; q++) {
            a2 += gelu_f(ha[q].f[0]) * s_hw2[k * 32 + 2 * q];
            a2 += gelu_f(ha[q].f[1]) * s_hw2[k * 32 + 2 * q + 1];
        }
        out[PV_OFF + b * NKNOWN + k] = sigm_f(a2);
    } else {
        atomicAdd(s_free + (s - NKNOWN), freeval);
    }
    __syncthreads();
    if (tid < NSLOT - NKNOWN) atomicAdd(out + FREE_OFF + tid, s_free[tid]);
}

// ================= launch =================
extern "C" void kernel_launch(void* const* d_in, const int* in_sizes, int n_in,
                              void* d_out, int out_size)
{
    const float* ws   = (const float*)d_in[0];
    const float* eps  = (const float*)d_in[1];
    const float* mu0  = (const float*)d_in[2];
    const float* sg0  = (const float*)d_in[3];
    const float* Wi   = (const float*)d_in[4];
    const float* bi   = (const float*)d_in[5];
    // d_in[6..9] = Wk, bk, Wq, bq : dead (attn == 1.0 exactly)
    const float* Wv   = (const float*)d_in[10];
    const float* bv   = (const float*)d_in[11];
    const float* Wih  = (const float*)d_in[12];
    const float* bih  = (const float*)d_in[13];
    const float* Whh  = (const float*)d_in[14];
    const float* bhh  = (const float*)d_in[15];
    const float* W1   = (const float*)d_in[16];
    const float* b1   = (const float*)d_in[17];
    const float* W2   = (const float*)d_in[18];
    const float* b2   = (const float*)d_in[19];
    const float* g_in = (const float*)d_in[20];
    const float* b_in = (const float*)d_in[21];
    // d_in[22..23] = g_sl, b_sl : dead
    const float* gm   = (const float*)d_in[24];
    const float* bm   = (const float*)d_in[25];
    const float* Wh1  = (const float*)d_in[26];
    const float* bh1  = (const float*)d_in[27];
    const float* Wh2  = (const float*)d_in[28];
    const float* bh2  = (const float*)d_in[29];
    float* out = (float*)d_out;

    size_t smemA = (size_t)SMEMA_FLOATS * sizeof(float);
    size_t smemB = (size_t)SMEMB_FLOATS * sizeof(float);
    cudaFuncSetAttribute(kA2, cudaFuncAttributeMaxDynamicSharedMemorySize, (int)smemA);
    cudaFuncSetAttribute(kB,  cudaFuncAttributeMaxDynamicSharedMemorySize, (int)smemB);

    kA2<<<B_TOTAL / 8, 512, smemA>>>(ws, Wi, bi, g_in, b_in, Wv, bv, Wih, bih);
    kZ<<<1, 32>>>(out);
    kB<<<B_TOTAL / 8, 256, smemB>>>(eps, mu0, sg0, Whh, bhh, W1, b1, W2, b2,
                                    gm, bm, Wh1, bh1, Wh2, bh2, out);
}